// round 5
// baseline (speedup 1.0000x reference)
#include <cuda_runtime.h>
#include <math.h>

#define SEQ    512
#define BATCH  64
#define NF     1024
#define STEP_ELEMS (BATCH * NF)   // 65536
#define KSPLIT 16
#define NTILES 16
#define NCTA   (KSPLIT * NTILES)  // 256 persistent CTAs

// Scratch (allocation-free rule: __device__ globals)
static __device__ float g_xproj[(size_t)SEQ * BATCH * NF];   // [s][b][h] 128 MB
static __device__ float g_hs[(size_t)SEQ * BATCH * NF];      // [s][b][h] 128 MB
static __device__ float g_part[(size_t)KSPLIT * BATCH * NF]; // partials   4 MB

// Grid-barrier state (zero-initialized; self-sustaining across graph replays:
// gen is monotonic, each barrier's last arriver resets the opposite counter)
static __device__ unsigned g_gen;
static __device__ unsigned g_cnt[2];

__device__ __forceinline__ void grid_barrier()
{
    __syncthreads();
    __threadfence();
    if (threadIdx.x == 0) {
        unsigned gen = *(volatile unsigned*)&g_gen;
        unsigned idx = gen & 1u;
        if (atomicAdd(&g_cnt[idx], 1u) == NCTA - 1u) {
            atomicExch(&g_cnt[idx ^ 1u], 0u);   // reset counter for barrier gen+2
            __threadfence();
            atomicAdd(&g_gen, 1u);
        } else {
            while (*(volatile unsigned*)&g_gen == gen) { __nanosleep(32); }
        }
        __threadfence();
    }
    __syncthreads();
}

// ---------------------------------------------------------------------------
// Bulk GEMM: C(32768 x 1024) = A(32768 x 1024) * Bw(1024 x 1024)^T + bias
//   mode 0: A = x      (row m = b*512+s), C -> g_xproj[s][b][n]
//   mode 1: A = g_hs   (row m = s*64+b),  C -> out[b][s][n]
// ---------------------------------------------------------------------------
__global__ __launch_bounds__(256, 2)
void big_gemm(const float* __restrict__ Ain,
              const float* __restrict__ Bw, int ldb,
              const float* __restrict__ bias,
              float* __restrict__ Cout, int mode)
{
    __shared__ float As[8][132];
    __shared__ float Bs[8][132];

    const float* __restrict__ A = (mode == 1) ? g_hs : Ain;
    float* __restrict__ C = (mode == 0) ? g_xproj : Cout;

    const int tid  = threadIdx.x;
    const int m0   = blockIdx.y * 128;
    const int n0   = blockIdx.x * 128;
    const int tr   = tid >> 4;
    const int tc   = tid & 15;
    const int lrow = tid >> 1;
    const int lcol = (tid & 1) * 4;

    float acc[8][8];
#pragma unroll
    for (int i = 0; i < 8; i++)
#pragma unroll
        for (int j = 0; j < 8; j++) acc[i][j] = 0.0f;

    const float* Ap = A  + (size_t)(m0 + lrow) * NF  + lcol;
    const float* Bp = Bw + (size_t)(n0 + lrow) * ldb + lcol;

    for (int k0 = 0; k0 < NF; k0 += 8) {
        float4 av = *(const float4*)(Ap + k0);
        float4 bv = *(const float4*)(Bp + k0);
        As[lcol + 0][lrow] = av.x;
        As[lcol + 1][lrow] = av.y;
        As[lcol + 2][lrow] = av.z;
        As[lcol + 3][lrow] = av.w;
        Bs[lcol + 0][lrow] = bv.x;
        Bs[lcol + 1][lrow] = bv.y;
        Bs[lcol + 2][lrow] = bv.z;
        Bs[lcol + 3][lrow] = bv.w;
        __syncthreads();
#pragma unroll
        for (int kk = 0; kk < 8; kk++) {
            float a[8], b[8];
            *(float4*)(a)     = *(const float4*)&As[kk][tr * 4];
            *(float4*)(a + 4) = *(const float4*)&As[kk][64 + tr * 4];
            *(float4*)(b)     = *(const float4*)&Bs[kk][tc * 4];
            *(float4*)(b + 4) = *(const float4*)&Bs[kk][64 + tc * 4];
#pragma unroll
            for (int i = 0; i < 8; i++)
#pragma unroll
                for (int j = 0; j < 8; j++)
                    acc[i][j] += a[i] * b[j];
        }
        __syncthreads();
    }

#pragma unroll
    for (int i = 0; i < 8; i++) {
        int mloc = (i < 4) ? (tr * 4 + i) : (64 + tr * 4 + (i - 4));
        int m = m0 + mloc;
        size_t crow;
        if (mode == 0) crow = (size_t)((m & 511) * 64  + (m >> 9)) * NF;  // [s][b]
        else           crow = (size_t)((m & 63)  * 512 + (m >> 6)) * NF;  // [b][s]
#pragma unroll
        for (int j = 0; j < 8; j++) {
            int n = n0 + ((j < 4) ? (tc * 4 + j) : (64 + tc * 4 + (j - 4)));
            C[crow + n] = acc[i][j] + bias[n];
        }
    }
}

// ---------------------------------------------------------------------------
// Persistent recurrence: ONE launch runs all 512 steps.
// Grid: 256 CTAs = 16 N-tiles(64) x 16 K-chunks(64). 128 threads, 8x4/thread.
// Per step: partial GEMM -> barrier -> reduce(+xproj)+tanh -> barrier.
// W_h slice is staged in SMEM once (loop-invariant).
// ---------------------------------------------------------------------------
__global__ __launch_bounds__(128, 2)
void rnn_recurrence(const float* __restrict__ h0,
                    const float* __restrict__ W_ih)
{
    __shared__ float Ws[64][68];   // Ws[k][n]
    __shared__ float Hs[64][68];   // Hs[k][m]

    const int tid = threadIdx.x;
    const int nt  = blockIdx.x & 15;
    const int kc  = blockIdx.x >> 4;
    const int n0  = nt * 64;
    const int k0  = kc * 64;
    const float* __restrict__ Wh = W_ih + NF;   // W_ih[:, 1024:2048]

    // Stage W_h slice (rows n0..n0+63, cols k0..k0+63), transposed.
    {
        int row = tid >> 1;
        int cg  = (tid & 1) * 32;
        const float* src = Wh + (size_t)(n0 + row) * 2048 + k0 + cg;
#pragma unroll
        for (int kk = 0; kk < 32; kk += 4) {
            float4 v = *(const float4*)(src + kk);
            Ws[cg + kk + 0][row] = v.x;
            Ws[cg + kk + 1][row] = v.y;
            Ws[cg + kk + 2][row] = v.z;
            Ws[cg + kk + 3][row] = v.w;
        }
    }

    const int tr = tid >> 4;   // 0..7  -> m = tr*8 + i
    const int tc = tid & 15;   // 0..15 -> n = tc*4 + j

    for (int s = 0; s < SEQ; s++) {
        const float* __restrict__ H =
            (s == 0) ? h0 : (g_hs + (size_t)(s - 1) * STEP_ELEMS);

        // Stage H chunk (rows 0..63, cols k0..k0+63), transposed.
        {
            int row = tid >> 1;
            int cg  = (tid & 1) * 32;
            const float* src = H + (size_t)row * NF + k0 + cg;
#pragma unroll
            for (int kk = 0; kk < 32; kk += 4) {
                float4 v = *(const float4*)(src + kk);
                Hs[cg + kk + 0][row] = v.x;
                Hs[cg + kk + 1][row] = v.y;
                Hs[cg + kk + 2][row] = v.z;
                Hs[cg + kk + 3][row] = v.w;
            }
        }
        __syncthreads();

        float acc[8][4];
#pragma unroll
        for (int i = 0; i < 8; i++)
#pragma unroll
            for (int j = 0; j < 4; j++) acc[i][j] = 0.0f;

#pragma unroll 8
        for (int kk = 0; kk < 64; kk++) {
            float a[8], b[4];
            *(float4*)(a)     = *(const float4*)&Hs[kk][tr * 8];
            *(float4*)(a + 4) = *(const float4*)&Hs[kk][tr * 8 + 4];
            *(float4*)(b)     = *(const float4*)&Ws[kk][tc * 4];
#pragma unroll
            for (int i = 0; i < 8; i++)
#pragma unroll
                for (int j = 0; j < 4; j++)
                    acc[i][j] += a[i] * b[j];
        }

        // Write 64x64 partial tile for this K-chunk.
        float* P = g_part + (size_t)kc * STEP_ELEMS;
#pragma unroll
        for (int i = 0; i < 8; i++) {
            int m = tr * 8 + i;
            *(float4*)&P[(size_t)m * NF + n0 + tc * 4] =
                make_float4(acc[i][0], acc[i][1], acc[i][2], acc[i][3]);
        }

        grid_barrier();   // all partials visible

        // Fused reduce + tanh: this CTA handles 256 outputs.
        {
            int base = blockIdx.x * 256 + tid * 2;
            float2 v = *(const float2*)&g_xproj[(size_t)s * STEP_ELEMS + base];
#pragma unroll
            for (int j = 0; j < KSPLIT; j++) {
                float2 p = *(const float2*)&g_part[(size_t)j * STEP_ELEMS + base];
                v.x += p.x;
                v.y += p.y;
            }
            float2 hh = make_float2(tanhf(v.x), tanhf(v.y));
            *(float2*)&g_hs[(size_t)s * STEP_ELEMS + base] = hh;
        }

        grid_barrier();   // h(s) visible; g_part safe to overwrite
    }
}

// ---------------------------------------------------------------------------
extern "C" void kernel_launch(void* const* d_in, const int* in_sizes, int n_in,
                              void* d_out, int out_size)
{
    const float* x    = (const float*)d_in[0];
    const float* h0   = (const float*)d_in[1];
    const float* W_ih = (const float*)d_in[2];
    const float* b_ih = (const float*)d_in[3];
    const float* W_ho = (const float*)d_in[4];
    const float* b_ho = (const float*)d_in[5];
    float* out = (float*)d_out;

    // Node 1: x_proj = x @ W_x^T + b_ih  ->  g_xproj[s][b][h]
    big_gemm<<<dim3(8, 256), 256>>>(x, W_ih, 2048, b_ih, nullptr, 0);

    // Node 2: all 512 recurrence steps in one persistent kernel
    rnn_recurrence<<<NCTA, 128>>>(h0, W_ih);

    // Node 3: out = Hs @ W_ho^T + b_ho   ->  out[b][s][o]
    big_gemm<<<dim3(8, 256), 256>>>(nullptr, W_ho, 1024, b_ho, out, 1);
}

// round 7
// speedup vs baseline: 1.0002x; 1.0002x over previous
#include <cuda_runtime.h>
#include <math.h>

#define SEQ    512
#define BATCH  64
#define NF     1024
#define STEP_ELEMS (BATCH * NF)   // 65536
#define KSPLIT 16
#define NTILES 16
#define NCTA   (KSPLIT * NTILES)  // 256 persistent CTAs

// Scratch (allocation-free rule: __device__ globals)
static __device__ float g_xproj[(size_t)SEQ * BATCH * NF];   // [s][b][h] 128 MB
static __device__ float g_hs[(size_t)SEQ * BATCH * NF];      // [s][b][h] 128 MB
static __device__ float g_part[(size_t)KSPLIT * BATCH * NF]; // partials   4 MB

// Grid-barrier state (zero-initialized; self-sustaining across graph replays:
// gen is monotonic, each barrier's last arriver resets the opposite counter)
static __device__ unsigned g_gen;
static __device__ unsigned g_cnt[2];

__device__ __forceinline__ void grid_barrier()
{
    __syncthreads();
    __threadfence();
    if (threadIdx.x == 0) {
        unsigned gen = *(volatile unsigned*)&g_gen;
        unsigned idx = gen & 1u;
        if (atomicAdd(&g_cnt[idx], 1u) == NCTA - 1u) {
            atomicExch(&g_cnt[idx ^ 1u], 0u);   // reset counter for barrier gen+2
            __threadfence();
            atomicAdd(&g_gen, 1u);
        } else {
            while (*(volatile unsigned*)&g_gen == gen) { __nanosleep(32); }
        }
        __threadfence();
    }
    __syncthreads();
}

// ---------------------------------------------------------------------------
// Bulk GEMM: C(32768 x 1024) = A(32768 x 1024) * Bw(1024 x 1024)^T + bias
//   mode 0: A = x      (row m = b*512+s), C -> g_xproj[s][b][n]
//   mode 1: A = g_hs   (row m = s*64+b),  C -> out[b][s][n]
// ---------------------------------------------------------------------------
__global__ __launch_bounds__(256, 2)
void big_gemm(const float* __restrict__ Ain,
              const float* __restrict__ Bw, int ldb,
              const float* __restrict__ bias,
              float* __restrict__ Cout, int mode)
{
    __shared__ float As[8][132];
    __shared__ float Bs[8][132];

    const float* __restrict__ A = (mode == 1) ? g_hs : Ain;
    float* __restrict__ C = (mode == 0) ? g_xproj : Cout;

    const int tid  = threadIdx.x;
    const int m0   = blockIdx.y * 128;
    const int n0   = blockIdx.x * 128;
    const int tr   = tid >> 4;
    const int tc   = tid & 15;
    const int lrow = tid >> 1;
    const int lcol = (tid & 1) * 4;

    float acc[8][8];
#pragma unroll
    for (int i = 0; i < 8; i++)
#pragma unroll
        for (int j = 0; j < 8; j++) acc[i][j] = 0.0f;

    const float* Ap = A  + (size_t)(m0 + lrow) * NF  + lcol;
    const float* Bp = Bw + (size_t)(n0 + lrow) * ldb + lcol;

    for (int k0 = 0; k0 < NF; k0 += 8) {
        float4 av = *(const float4*)(Ap + k0);
        float4 bv = *(const float4*)(Bp + k0);
        As[lcol + 0][lrow] = av.x;
        As[lcol + 1][lrow] = av.y;
        As[lcol + 2][lrow] = av.z;
        As[lcol + 3][lrow] = av.w;
        Bs[lcol + 0][lrow] = bv.x;
        Bs[lcol + 1][lrow] = bv.y;
        Bs[lcol + 2][lrow] = bv.z;
        Bs[lcol + 3][lrow] = bv.w;
        __syncthreads();
#pragma unroll
        for (int kk = 0; kk < 8; kk++) {
            float a[8], b[8];
            *(float4*)(a)     = *(const float4*)&As[kk][tr * 4];
            *(float4*)(a + 4) = *(const float4*)&As[kk][64 + tr * 4];
            *(float4*)(b)     = *(const float4*)&Bs[kk][tc * 4];
            *(float4*)(b + 4) = *(const float4*)&Bs[kk][64 + tc * 4];
#pragma unroll
            for (int i = 0; i < 8; i++)
#pragma unroll
                for (int j = 0; j < 8; j++)
                    acc[i][j] += a[i] * b[j];
        }
        __syncthreads();
    }

#pragma unroll
    for (int i = 0; i < 8; i++) {
        int mloc = (i < 4) ? (tr * 4 + i) : (64 + tr * 4 + (i - 4));
        int m = m0 + mloc;
        size_t crow;
        if (mode == 0) crow = (size_t)((m & 511) * 64  + (m >> 9)) * NF;  // [s][b]
        else           crow = (size_t)((m & 63)  * 512 + (m >> 6)) * NF;  // [b][s]
#pragma unroll
        for (int j = 0; j < 8; j++) {
            int n = n0 + ((j < 4) ? (tc * 4 + j) : (64 + tc * 4 + (j - 4)));
            C[crow + n] = acc[i][j] + bias[n];
        }
    }
}

// ---------------------------------------------------------------------------
// Persistent recurrence: ONE launch runs all 512 steps.
// Grid: 256 CTAs = 16 N-tiles(64) x 16 K-chunks(64). 128 threads, 8x4/thread.
// Per step: partial GEMM -> barrier -> reduce(+xproj)+tanh -> barrier.
// W_h slice is staged in SMEM once (loop-invariant).
// ---------------------------------------------------------------------------
__global__ __launch_bounds__(128, 2)
void rnn_recurrence(const float* __restrict__ h0,
                    const float* __restrict__ W_ih)
{
    __shared__ float Ws[64][68];   // Ws[k][n]
    __shared__ float Hs[64][68];   // Hs[k][m]

    const int tid = threadIdx.x;
    const int nt  = blockIdx.x & 15;
    const int kc  = blockIdx.x >> 4;
    const int n0  = nt * 64;
    const int k0  = kc * 64;
    const float* __restrict__ Wh = W_ih + NF;   // W_ih[:, 1024:2048]

    // Stage W_h slice (rows n0..n0+63, cols k0..k0+63), transposed.
    {
        int row = tid >> 1;
        int cg  = (tid & 1) * 32;
        const float* src = Wh + (size_t)(n0 + row) * 2048 + k0 + cg;
#pragma unroll
        for (int kk = 0; kk < 32; kk += 4) {
            float4 v = *(const float4*)(src + kk);
            Ws[cg + kk + 0][row] = v.x;
            Ws[cg + kk + 1][row] = v.y;
            Ws[cg + kk + 2][row] = v.z;
            Ws[cg + kk + 3][row] = v.w;
        }
    }

    const int tr = tid >> 4;   // 0..7  -> m = tr*8 + i
    const int tc = tid & 15;   // 0..15 -> n = tc*4 + j

    for (int s = 0; s < SEQ; s++) {
        const float* __restrict__ H =
            (s == 0) ? h0 : (g_hs + (size_t)(s - 1) * STEP_ELEMS);

        // Stage H chunk (rows 0..63, cols k0..k0+63), transposed.
        {
            int row = tid >> 1;
            int cg  = (tid & 1) * 32;
            const float* src = H + (size_t)row * NF + k0 + cg;
#pragma unroll
            for (int kk = 0; kk < 32; kk += 4) {
                float4 v = *(const float4*)(src + kk);
                Hs[cg + kk + 0][row] = v.x;
                Hs[cg + kk + 1][row] = v.y;
                Hs[cg + kk + 2][row] = v.z;
                Hs[cg + kk + 3][row] = v.w;
            }
        }
        __syncthreads();

        float acc[8][4];
#pragma unroll
        for (int i = 0; i < 8; i++)
#pragma unroll
            for (int j = 0; j < 4; j++) acc[i][j] = 0.0f;

#pragma unroll 8
        for (int kk = 0; kk < 64; kk++) {
            float a[8], b[4];
            *(float4*)(a)     = *(const float4*)&Hs[kk][tr * 8];
            *(float4*)(a + 4) = *(const float4*)&Hs[kk][tr * 8 + 4];
            *(float4*)(b)     = *(const float4*)&Ws[kk][tc * 4];
#pragma unroll
            for (int i = 0; i < 8; i++)
#pragma unroll
                for (int j = 0; j < 4; j++)
                    acc[i][j] += a[i] * b[j];
        }

        // Write 64x64 partial tile for this K-chunk.
        float* P = g_part + (size_t)kc * STEP_ELEMS;
#pragma unroll
        for (int i = 0; i < 8; i++) {
            int m = tr * 8 + i;
            *(float4*)&P[(size_t)m * NF + n0 + tc * 4] =
                make_float4(acc[i][0], acc[i][1], acc[i][2], acc[i][3]);
        }

        grid_barrier();   // all partials visible

        // Fused reduce + tanh: this CTA handles 256 outputs.
        {
            int base = blockIdx.x * 256 + tid * 2;
            float2 v = *(const float2*)&g_xproj[(size_t)s * STEP_ELEMS + base];
#pragma unroll
            for (int j = 0; j < KSPLIT; j++) {
                float2 p = *(const float2*)&g_part[(size_t)j * STEP_ELEMS + base];
                v.x += p.x;
                v.y += p.y;
            }
            float2 hh = make_float2(tanhf(v.x), tanhf(v.y));
            *(float2*)&g_hs[(size_t)s * STEP_ELEMS + base] = hh;
        }

        grid_barrier();   // h(s) visible; g_part safe to overwrite
    }
}

// ---------------------------------------------------------------------------
extern "C" void kernel_launch(void* const* d_in, const int* in_sizes, int n_in,
                              void* d_out, int out_size)
{
    const float* x    = (const float*)d_in[0];
    const float* h0   = (const float*)d_in[1];
    const float* W_ih = (const float*)d_in[2];
    const float* b_ih = (const float*)d_in[3];
    const float* W_ho = (const float*)d_in[4];
    const float* b_ho = (const float*)d_in[5];
    float* out = (float*)d_out;

    // Node 1: x_proj = x @ W_x^T + b_ih  ->  g_xproj[s][b][h]
    big_gemm<<<dim3(8, 256), 256>>>(x, W_ih, 2048, b_ih, nullptr, 0);

    // Node 2: all 512 recurrence steps in one persistent kernel
    rnn_recurrence<<<NCTA, 128>>>(h0, W_ih);

    // Node 3: out = Hs @ W_ho^T + b_ho   ->  out[b][s][o]
    big_gemm<<<dim3(8, 256), 256>>>(nullptr, W_ho, 1024, b_ho, out, 1);
}